// round 1
// baseline (speedup 1.0000x reference)
#include <cuda_runtime.h>
#include <math_constants.h>
#include <cstdint>

#define DD 256      // embedding dim (fixed for this problem)
#define BK 8        // d-chunk staged in smem per iteration
#define BT 128      // rows (tokens) per block tile
#define BN 128      // cols (codes) per K-tile
#define MAXT 65536
#define MAXK 4096

// Scratch (static __device__ — no allocation allowed)
__device__ float  g_A[MAXT];         // ||z_t||^2
__device__ float  g_C[MAXK];         // ||e_k||^2
__device__ int    g_idx[MAXT];       // argmin index per token
__device__ double g_part[MAXT / 32]; // per-block loss partials

// ---------------------------------------------------------------------------
// Kernel 1: squared L2 norms of all z rows and all codebook rows.
// One warp per row (256 floats = 64 float4; 2 float4 per lane).
// ---------------------------------------------------------------------------
__global__ void sq_norm_kernel(const float* __restrict__ z,
                               const float* __restrict__ E,
                               int T, int K)
{
    int warp = (int)((blockIdx.x * blockDim.x + threadIdx.x) >> 5);
    int lane = threadIdx.x & 31;
    int n = T + K;
    if (warp >= n) return;
    const float* src = (warp < T) ? (z + (size_t)warp * DD)
                                  : (E + (size_t)(warp - T) * DD);
    const float4* p = (const float4*)src;
    float s = 0.f;
    float4 v = p[lane];
    s += v.x * v.x + v.y * v.y + v.z * v.z + v.w * v.w;
    v = p[lane + 32];
    s += v.x * v.x + v.y * v.y + v.z * v.z + v.w * v.w;
    #pragma unroll
    for (int o = 16; o > 0; o >>= 1) s += __shfl_xor_sync(0xffffffffu, s, o);
    if (lane == 0) {
        if (warp < T) g_A[warp] = s;
        else          g_C[warp - T] = s;
    }
}

// ---------------------------------------------------------------------------
// Kernel 2: fused fp32 GEMM (z @ E^T) + distance + argmin.
// Block tile: 128 tokens x full K (looped in 128-code tiles).
// Thread microtile 8x8; smem staged As[d][row] / Bs[d][col]; register
// prefetch of the next global chunk hides LDG latency under the FFMA loop.
// Distance replicates jax op order: fl(fl(A - 2m) + C); argmin tie-breaks
// to lowest index (ascending scan + strict <, explicit tie-break in the
// cross-thread reduction).
// ---------------------------------------------------------------------------
__global__ __launch_bounds__(256)
void vq_argmin_kernel(const float* __restrict__ z,
                      const float* __restrict__ E,
                      int T, int K)
{
    __shared__ float As[BK][BT];
    __shared__ float Bs[BK][BN];
    __shared__ float Cs[BN];
    __shared__ float sval[BT][16];
    __shared__ int   sidx[BT][16];

    const int tid = threadIdx.x;
    const int tx = tid & 15;    // col group
    const int ty = tid >> 4;    // row group
    const int row0 = blockIdx.x * BT;

    // loader mapping: 256 threads cover 128 rows x 8 d (one float4 each)
    const int lr = tid >> 1;    // 0..127
    const int lq = tid & 1;     // which half of the 8-wide d chunk

    float bv[8];
    int   bi[8];
    float av[8];
    #pragma unroll
    for (int i = 0; i < 8; i++) { bv[i] = CUDART_INF_F; bi[i] = 0; }
    #pragma unroll
    for (int i = 0; i < 8; i++) {
        int r = (i < 4) ? (4 * ty + i) : (64 + 4 * ty + (i - 4));
        av[i] = g_A[row0 + r];
    }

    const int nkt = K / BN;   // 32
    const int ndc = DD / BK;  // 32

    // prefetch chunk (kb=0, dc=0)
    float4 fz = *(const float4*)(z + (size_t)(row0 + lr) * DD + 4 * lq);
    float4 fe = *(const float4*)(E + (size_t)lr * DD + 4 * lq);

    for (int kb = 0; kb < nkt; kb++) {
        float acc[8][8];
        #pragma unroll
        for (int i = 0; i < 8; i++)
            #pragma unroll
            for (int j = 0; j < 8; j++) acc[i][j] = 0.f;

        if (tid < BN) Cs[tid] = g_C[kb * BN + tid];

        for (int dc = 0; dc < ndc; dc++) {
            __syncthreads();   // previous compute / Cs reads done
            As[4 * lq + 0][lr] = fz.x;
            As[4 * lq + 1][lr] = fz.y;
            As[4 * lq + 2][lr] = fz.z;
            As[4 * lq + 3][lr] = fz.w;
            Bs[4 * lq + 0][lr] = fe.x;
            Bs[4 * lq + 1][lr] = fe.y;
            Bs[4 * lq + 2][lr] = fe.z;
            Bs[4 * lq + 3][lr] = fe.w;
            __syncthreads();

            // prefetch next chunk into registers (hidden under compute)
            int dc2 = dc + 1, kb2 = kb;
            if (dc2 == ndc) { dc2 = 0; kb2++; }
            if (kb2 < nkt) {
                fz = *(const float4*)(z + (size_t)(row0 + lr) * DD + dc2 * BK + 4 * lq);
                fe = *(const float4*)(E + (size_t)(kb2 * BN + lr) * DD + dc2 * BK + 4 * lq);
            }

            #pragma unroll
            for (int d = 0; d < BK; d++) {
                float4 a0 = *(const float4*)&As[d][4 * ty];
                float4 a1 = *(const float4*)&As[d][64 + 4 * ty];
                float4 b0 = *(const float4*)&Bs[d][4 * tx];
                float4 b1 = *(const float4*)&Bs[d][64 + 4 * tx];
                float a[8] = {a0.x, a0.y, a0.z, a0.w, a1.x, a1.y, a1.z, a1.w};
                float b[8] = {b0.x, b0.y, b0.z, b0.w, b1.x, b1.y, b1.z, b1.w};
                #pragma unroll
                for (int i = 0; i < 8; i++)
                    #pragma unroll
                    for (int j = 0; j < 8; j++)
                        acc[i][j] = fmaf(a[i], b[j], acc[i][j]);
            }
        }

        // epilogue: distances + running argmin (k ascending within thread)
        #pragma unroll
        for (int i = 0; i < 8; i++) {
            #pragma unroll
            for (int j = 0; j < 8; j++) {
                int c = (j < 4) ? (4 * tx + j) : (64 + 4 * tx + (j - 4));
                // jax: (A - 2m) + C ; fma(-2,m,A) == A - fl(2m) exactly
                float dval = fmaf(-2.0f, acc[i][j], av[i]) + Cs[c];
                int kidx = kb * BN + c;
                if (dval < bv[i]) { bv[i] = dval; bi[i] = kidx; }
            }
        }
        __syncthreads();  // protect Cs before next kb overwrites it
    }

    // cross-thread reduction (16 col-threads per row), lowest-index tiebreak
    #pragma unroll
    for (int i = 0; i < 8; i++) {
        int r = (i < 4) ? (4 * ty + i) : (64 + 4 * ty + (i - 4));
        sval[r][tx] = bv[i];
        sidx[r][tx] = bi[i];
    }
    __syncthreads();
    if (tid < BT) {
        float v = sval[tid][0];
        int   b = sidx[tid][0];
        #pragma unroll
        for (int t = 1; t < 16; t++) {
            float v2 = sval[tid][t];
            int   b2 = sidx[tid][t];
            if (v2 < v || (v2 == v && b2 < b)) { v = v2; b = b2; }
        }
        g_idx[row0 + tid] = b;
    }
}

// ---------------------------------------------------------------------------
// Kernel 3: gather quantized rows, write indices (as float), accumulate
// per-block loss partials in double (deterministic tree reduction).
// One block = 32 rows; thread = one of 256 columns.
// ---------------------------------------------------------------------------
__global__ void vq_gather_kernel(const float* __restrict__ z,
                                 const float* __restrict__ E,
                                 float* __restrict__ out,
                                 int T, int with_idx)
{
    __shared__ double sred[256];
    int tid = threadIdx.x;
    int rbase = blockIdx.x * 32;
    double acc = 0.0;
    for (int rr = 0; rr < 32; rr++) {
        int row = rbase + rr;
        int k = g_idx[row];
        float e  = E[(size_t)k * DD + tid];
        float zv = z[(size_t)row * DD + tid];
        out[(size_t)row * DD + tid] = e;
        float dlt = e - zv;
        acc += (double)dlt * (double)dlt;
        if (with_idx && tid == 0) out[(size_t)T * DD + row] = (float)k;
    }
    sred[tid] = acc;
    __syncthreads();
    #pragma unroll
    for (int o = 128; o > 0; o >>= 1) {
        if (tid < o) sred[tid] += sred[tid + o];
        __syncthreads();
    }
    if (tid == 0) g_part[blockIdx.x] = sred[0];
}

// ---------------------------------------------------------------------------
// Kernel 4: final loss reduction. loss = m + 0.25*m in fp32 (jax op order).
// ---------------------------------------------------------------------------
__global__ void vq_loss_kernel(float* __restrict__ out, int T, int npart)
{
    __shared__ double sred[256];
    int tid = threadIdx.x;
    double acc = 0.0;
    for (int i = tid; i < npart; i += 256) acc += g_part[i];
    sred[tid] = acc;
    __syncthreads();
    #pragma unroll
    for (int o = 128; o > 0; o >>= 1) {
        if (tid < o) sred[tid] += sred[tid + o];
        __syncthreads();
    }
    if (tid == 0) {
        float m = (float)(sred[0] / ((double)T * (double)DD));
        out[(size_t)T * DD + T] = m + 0.25f * m;
    }
}

// ---------------------------------------------------------------------------
extern "C" void kernel_launch(void* const* d_in, const int* in_sizes, int n_in,
                              void* d_out, int out_size)
{
    const float* z = (const float*)d_in[0];
    const float* E = (const float*)d_in[1];
    float* out = (float*)d_out;

    int T = in_sizes[0] / DD;   // 65536
    int K = in_sizes[1] / DD;   // 4096

    int nrows = T + K;
    int nblk1 = (nrows * 32 + 255) / 256;
    sq_norm_kernel<<<nblk1, 256>>>(z, E, T, K);

    vq_argmin_kernel<<<T / BT, 256>>>(z, E, T, K);

    long long need_idx  = (long long)T * DD + T;
    int with_idx = (out_size >= need_idx) ? 1 : 0;
    vq_gather_kernel<<<T / 32, 256>>>(z, E, out, T, with_idx);

    if (out_size >= need_idx + 1)
        vq_loss_kernel<<<1, 256>>>(out, T, T / 32);
}

// round 3
// speedup vs baseline: 6.3372x; 6.3372x over previous
#include <cuda_runtime.h>
#include <cuda_bf16.h>
#include <math_constants.h>
#include <cstdint>

#define DD 256        // embedding dim
#define TT 65536      // tokens
#define KK 4096       // codes

// ---------------- scratch globals (no allocation allowed) ------------------
__device__ __align__(16) __nv_bfloat16 g_Abf[(size_t)TT * DD]; // z in bf16
__device__ __align__(16) __nv_bfloat16 g_Ebf[(size_t)KK * DD]; // codebook bf16
__device__ float  g_A[TT];                // ||z||^2
__device__ float  g_C[KK];                // ||e||^2
__device__ float  g_cv[(size_t)TT * 16];  // approx candidates (values)
__device__ int    g_ci[(size_t)TT * 16];  // approx candidates (indices)
__device__ int    g_idx[TT];
__device__ double g_part[TT / 32];

// ---------------- PTX helpers (plain sm_103-compatible) --------------------
__device__ __forceinline__ uint32_t smem_u32(const void* p) {
    uint32_t a;
    asm("{ .reg .u64 t; cvta.to.shared.u64 t, %1; cvt.u32.u64 %0, t; }"
        : "=r"(a) : "l"(p));
    return a;
}
__device__ __forceinline__ void cp16(uint32_t dst, const void* src) {
    asm volatile("cp.async.cg.shared.global [%0], [%1], 16;"
                 :: "r"(dst), "l"(src));
}
__device__ __forceinline__ void cp_commit() {
    asm volatile("cp.async.commit_group;" ::: "memory");
}
template <int N>
__device__ __forceinline__ void cp_wait() {
    asm volatile("cp.async.wait_group %0;" :: "n"(N) : "memory");
}
__device__ __forceinline__ void ldm_x4(uint32_t* r, uint32_t addr) {
    asm volatile("ldmatrix.sync.aligned.m8n8.x4.shared.b16 {%0,%1,%2,%3}, [%4];"
                 : "=r"(r[0]), "=r"(r[1]), "=r"(r[2]), "=r"(r[3]) : "r"(addr));
}
__device__ __forceinline__ void mma16816(float* d, const uint32_t* a,
                                         const uint32_t* b) {
    asm volatile(
        "mma.sync.aligned.m16n8k16.row.col.f32.bf16.bf16.f32 "
        "{%0,%1,%2,%3}, {%4,%5,%6,%7}, {%8,%9}, {%0,%1,%2,%3};"
        : "+f"(d[0]), "+f"(d[1]), "+f"(d[2]), "+f"(d[3])
        : "r"(a[0]), "r"(a[1]), "r"(a[2]), "r"(a[3]), "r"(b[0]), "r"(b[1]));
}
// Swizzled smem tile offset: rows of 512B (256 bf16), XOR-swizzle inside 128B.
__device__ __forceinline__ uint32_t tile_off(int r, int kbyte) {
    return (uint32_t)(r * 512 + (kbyte & ~127) + ((kbyte & 127) ^ ((r & 7) << 4)));
}

#define SM_A      0
#define SM_B(p)   (65536 + (p) * 65536)
#define SMEM_TOTAL (3 * 65536)

// ---------------------------------------------------------------------------
// Kernel 1: norms + bf16 conversion of z and E. One warp per row.
// ---------------------------------------------------------------------------
__global__ void prep_kernel(const float* __restrict__ z,
                            const float* __restrict__ E, int T, int K)
{
    int warp = (int)((blockIdx.x * blockDim.x + threadIdx.x) >> 5);
    int lane = threadIdx.x & 31;
    if (warp >= T + K) return;
    const float* src = (warp < T) ? (z + (size_t)warp * DD)
                                  : (E + (size_t)(warp - T) * DD);
    const float4* p = (const float4*)src;
    float4 a = p[lane], b = p[lane + 32];
    float s = a.x*a.x + a.y*a.y + a.z*a.z + a.w*a.w
            + b.x*b.x + b.y*b.y + b.z*b.z + b.w*b.w;
    #pragma unroll
    for (int o = 16; o > 0; o >>= 1) s += __shfl_xor_sync(0xffffffffu, s, o);

    __nv_bfloat162* dst = (warp < T)
        ? (__nv_bfloat162*)(g_Abf + (size_t)warp * DD)
        : (__nv_bfloat162*)(g_Ebf + (size_t)(warp - T) * DD);
    dst[2*lane + 0]      = __float22bfloat162_rn(make_float2(a.x, a.y));
    dst[2*lane + 1]      = __float22bfloat162_rn(make_float2(a.z, a.w));
    dst[2*(lane+32) + 0] = __float22bfloat162_rn(make_float2(b.x, b.y));
    dst[2*(lane+32) + 1] = __float22bfloat162_rn(make_float2(b.z, b.w));

    if (lane == 0) {
        if (warp < T) g_A[warp] = s;
        else          g_C[warp - T] = s;
    }
}

// ---------------------------------------------------------------------------
// Kernel 2: bf16 HMMA GEMM (z_bf @ E_bf^T) + per-token top-2-per-stripe.
// CTA: 128 tokens x 128 codes per iter, 32 code tiles. 4 warps, 64x64 each.
// A tile resident in smem; B double-buffered via cp.async.
// ---------------------------------------------------------------------------
#define TOP2(q, s, c) do {                                                    \
    if ((s) < tv[q][1]) {                                                     \
        if ((s) < tv[q][0]) { tv[q][1]=tv[q][0]; ti[q][1]=ti[q][0];           \
                              tv[q][0]=(s); ti[q][0]=(c); }                   \
        else { tv[q][1]=(s); ti[q][1]=(c); }                                  \
    } } while (0)

__global__ __launch_bounds__(128, 1) void vq_mma_kernel()
{
    extern __shared__ char smem[];
    const uint32_t sa = smem_u32(smem);
    const int tid = threadIdx.x;
    const int row0 = blockIdx.x * 128;

    // ---- stage A (resident) + B tile 0, one cp.async group ----
    {
        const char* srcA = (const char*)g_Abf + (size_t)row0 * 512;
        const char* srcB = (const char*)g_Ebf;
        #pragma unroll
        for (int i = 0; i < 32; i++) {
            int idx = i * 128 + tid;
            int r = idx >> 5, c = idx & 31;
            cp16(sa + SM_A + tile_off(r, c * 16), srcA + (size_t)r * 512 + c * 16);
        }
        #pragma unroll
        for (int i = 0; i < 32; i++) {
            int idx = i * 128 + tid;
            int r = idx >> 5, c = idx & 31;
            cp16(sa + SM_B(0) + tile_off(r, c * 16), srcB + (size_t)r * 512 + c * 16);
        }
        cp_commit();
    }

    const int l = tid & 31, w = tid >> 5;
    const int wm = w >> 1, wn = w & 1;

    float tv[8][2]; int ti[8][2];
    #pragma unroll
    for (int q = 0; q < 8; q++) {
        tv[q][0] = tv[q][1] = CUDART_INF_F;
        ti[q][0] = ti[q][1] = 0x7fffffff;
    }

    // ldmatrix lane address components
    const int a_r  = l & 15;              // row within 16-row tile
    const int a_kb = (l >> 4) * 16;       // 8-elt (16B) half select
    const int b_r  = ((l >> 4) << 3) + (l & 7);
    const int b_kb = ((l >> 3) & 1) * 16;

    float acc[4][8][4];

    for (int kb = 0; kb < 32; kb++) {
        if (kb < 31) {       // prefetch next B tile
            const char* srcB = (const char*)g_Ebf + (size_t)(kb + 1) * 128 * 512;
            uint32_t db = sa + SM_B((kb + 1) & 1);
            #pragma unroll
            for (int i = 0; i < 32; i++) {
                int idx = i * 128 + tid;
                int r = idx >> 5, c = idx & 31;
                cp16(db + tile_off(r, c * 16), srcB + (size_t)r * 512 + c * 16);
            }
            cp_commit();
            cp_wait<1>();
        } else {
            cp_wait<0>();
        }
        __syncthreads();

        const uint32_t sB = sa + SM_B(kb & 1);

        #pragma unroll
        for (int mi = 0; mi < 4; mi++)
            #pragma unroll
            for (int ni = 0; ni < 8; ni++)
                #pragma unroll
                for (int j = 0; j < 4; j++) acc[mi][ni][j] = 0.f;

        #pragma unroll
        for (int ks = 0; ks < 16; ks++) {
            const int k0b = ks * 32;
            uint32_t afrag[4][4];
            #pragma unroll
            for (int mi = 0; mi < 4; mi++)
                ldm_x4(afrag[mi],
                       sa + SM_A + tile_off(wm * 64 + mi * 16 + a_r, k0b + a_kb));
            uint32_t bfrag[8][2];
            #pragma unroll
            for (int nj = 0; nj < 4; nj++) {
                uint32_t t4[4];
                ldm_x4(t4, sB + tile_off(wn * 64 + nj * 16 + b_r, k0b + b_kb));
                bfrag[2*nj][0]   = t4[0]; bfrag[2*nj][1]   = t4[1];
                bfrag[2*nj+1][0] = t4[2]; bfrag[2*nj+1][1] = t4[3];
            }
            #pragma unroll
            for (int mi = 0; mi < 4; mi++)
                #pragma unroll
                for (int ni = 0; ni < 8; ni++)
                    mma16816(acc[mi][ni], afrag[mi], bfrag[ni]);
        }

        // epilogue: s = -2*m + ||e||^2 ; per-row top2 (cols ascend: ni then j)
        #pragma unroll
        for (int ni = 0; ni < 8; ni++) {
            const int c0 = kb * 128 + wn * 64 + ni * 8 + (l & 3) * 2;
            const float2 C2 = __ldg((const float2*)(g_C + c0));
            #pragma unroll
            for (int mi = 0; mi < 4; mi++) {
                #pragma unroll
                for (int half = 0; half < 2; half++) {
                    const int q = mi * 2 + half;
                    float s0 = fmaf(-2.f, acc[mi][ni][half * 2 + 0], C2.x);
                    float s1 = fmaf(-2.f, acc[mi][ni][half * 2 + 1], C2.y);
                    TOP2(q, s0, c0);
                    TOP2(q, s1, c0 + 1);
                }
            }
        }
        __syncthreads();   // protect B buffer before next prefetch overwrites
    }

    // write 16 candidates per token (2 warps x 4 lane-cols x 2 entries)
    #pragma unroll
    for (int q = 0; q < 8; q++) {
        const int mi = q >> 1, half = q & 1;
        const int r = row0 + wm * 64 + mi * 16 + (l >> 2) + half * 8;
        const int base = r * 16 + wn * 8 + (l & 3) * 2;
        g_cv[base]     = tv[q][0];  g_cv[base + 1] = tv[q][1];
        g_ci[base]     = ti[q][0];  g_ci[base + 1] = ti[q][1];
    }
}

// ---------------------------------------------------------------------------
// Kernel 3: exact rescore of near-tie candidates (reference rounding
// fl(fl(A - 2m) + C), lowest-index tie-break). One warp per token.
// ---------------------------------------------------------------------------
__global__ void rescore_kernel(const float* __restrict__ z,
                               const float* __restrict__ E, int T)
{
    int warp = (int)((blockIdx.x * blockDim.x + threadIdx.x) >> 5);
    int lane = threadIdx.x & 31;
    if (warp >= T) return;
    const size_t t = (size_t)warp;

    float vL = CUDART_INF_F; int iL = 0x7fffffff;
    if (lane < 16) { vL = g_cv[t * 16 + lane]; iL = g_ci[t * 16 + lane]; }
    float v0 = vL;
    #pragma unroll
    for (int o = 16; o > 0; o >>= 1)
        v0 = fminf(v0, __shfl_xor_sync(0xffffffffu, v0, o));
    const float thr = v0 + 1.5e-4f;
    unsigned mask = __ballot_sync(0xffffffffu, vL <= thr);

    int besti;
    if (__popc(mask) == 1) {
        besti = __shfl_sync(0xffffffffu, iL, __ffs(mask) - 1);
    } else {
        const float4* zp = (const float4*)(z + t * DD);
        float4 z0 = zp[lane], z1 = zp[lane + 32];
        float A = g_A[t];
        float bd = CUDART_INF_F; besti = 0x7fffffff;
        #pragma unroll 1
        for (int c = 0; c < 16; c++) {
            if (!((mask >> c) & 1u)) continue;
            int ic = __shfl_sync(0xffffffffu, iL, c);
            const float4* ep = (const float4*)(E + (size_t)ic * DD);
            float4 e0 = ep[lane], e1 = ep[lane + 32];
            float pm = z0.x*e0.x + z0.y*e0.y + z0.z*e0.z + z0.w*e0.w
                     + z1.x*e1.x + z1.y*e1.y + z1.z*e1.z + z1.w*e1.w;
            #pragma unroll
            for (int o = 16; o > 0; o >>= 1)
                pm += __shfl_xor_sync(0xffffffffu, pm, o);
            float d = fmaf(-2.0f, pm, A) + g_C[ic];
            if (d < bd || (d == bd && ic < besti)) { bd = d; besti = ic; }
        }
    }
    if (lane == 0) g_idx[t] = besti;
}

// ---------------------------------------------------------------------------
// Kernel 4: gather quantized rows, write indices, loss partials (double).
// ---------------------------------------------------------------------------
__global__ void vq_gather_kernel(const float* __restrict__ z,
                                 const float* __restrict__ E,
                                 float* __restrict__ out,
                                 int T, int with_idx)
{
    __shared__ double sred[256];
    int tid = threadIdx.x;
    int rbase = blockIdx.x * 32;
    double acc = 0.0;
    for (int rr = 0; rr < 32; rr++) {
        int row = rbase + rr;
        int k = g_idx[row];
        float e  = E[(size_t)k * DD + tid];
        float zv = z[(size_t)row * DD + tid];
        out[(size_t)row * DD + tid] = e;
        float dlt = e - zv;
        acc += (double)dlt * (double)dlt;
        if (with_idx && tid == 0) out[(size_t)T * DD + row] = (float)k;
    }
    sred[tid] = acc;
    __syncthreads();
    #pragma unroll
    for (int o = 128; o > 0; o >>= 1) {
        if (tid < o) sred[tid] += sred[tid + o];
        __syncthreads();
    }
    if (tid == 0) g_part[blockIdx.x] = sred[0];
}

__global__ void vq_loss_kernel(float* __restrict__ out, int T, int npart)
{
    __shared__ double sred[256];
    int tid = threadIdx.x;
    double acc = 0.0;
    for (int i = tid; i < npart; i += 256) acc += g_part[i];
    sred[tid] = acc;
    __syncthreads();
    #pragma unroll
    for (int o = 128; o > 0; o >>= 1) {
        if (tid < o) sred[tid] += sred[tid + o];
        __syncthreads();
    }
    if (tid == 0) {
        float m = (float)(sred[0] / ((double)T * (double)DD));
        out[(size_t)T * DD + T] = m + 0.25f * m;
    }
}

// ---------------------------------------------------------------------------
extern "C" void kernel_launch(void* const* d_in, const int* in_sizes, int n_in,
                              void* d_out, int out_size)
{
    const float* z = (const float*)d_in[0];
    const float* E = (const float*)d_in[1];
    float* out = (float*)d_out;

    int T = in_sizes[0] / DD;   // 65536
    int K = in_sizes[1] / DD;   // 4096

    int nblk1 = ((T + K) * 32 + 255) / 256;
    prep_kernel<<<nblk1, 256>>>(z, E, T, K);

    cudaFuncSetAttribute(vq_mma_kernel,
                         cudaFuncAttributeMaxDynamicSharedMemorySize, SMEM_TOTAL);
    vq_mma_kernel<<<T / 128, 128, SMEM_TOTAL>>>();

    rescore_kernel<<<T / 8, 256>>>(z, E, T);

    long long need_idx = (long long)T * DD + T;
    int with_idx = (out_size >= need_idx) ? 1 : 0;
    vq_gather_kernel<<<T / 32, 256>>>(z, E, out, T, with_idx);

    if (out_size >= need_idx + 1)
        vq_loss_kernel<<<1, 256>>>(out, T, T / 32);
}

// round 4
// speedup vs baseline: 7.8087x; 1.2322x over previous
#include <cuda_runtime.h>
#include <cuda_bf16.h>
#include <math_constants.h>
#include <cstdint>

#define DD 256        // embedding dim
#define TT 65536      // tokens
#define KK 4096       // codes
#define TM 256        // tokens per CTA
#define TNB 64        // codes per B tile
#define NKB (KK / TNB) // 64 iterations

// ---------------- scratch globals (no allocation allowed) ------------------
__device__ __align__(16) __nv_bfloat16 g_Ebf[(size_t)KK * DD]; // codebook bf16
__device__ float  g_C[KK];                // ||e||^2
__device__ float  g_cv[(size_t)TT * 16];  // approx candidates (values)
__device__ int    g_ci[(size_t)TT * 16];  // approx candidates (indices)
__device__ int    g_idx[TT];
__device__ double g_part[TT / 32];

// ---------------- PTX helpers (plain sm_103-compatible) --------------------
__device__ __forceinline__ uint32_t smem_u32(const void* p) {
    uint32_t a;
    asm("{ .reg .u64 t; cvta.to.shared.u64 t, %1; cvt.u32.u64 %0, t; }"
        : "=r"(a) : "l"(p));
    return a;
}
__device__ __forceinline__ void cp16(uint32_t dst, const void* src) {
    asm volatile("cp.async.cg.shared.global [%0], [%1], 16;"
                 :: "r"(dst), "l"(src));
}
__device__ __forceinline__ void cp_commit() {
    asm volatile("cp.async.commit_group;" ::: "memory");
}
template <int N>
__device__ __forceinline__ void cp_wait() {
    asm volatile("cp.async.wait_group %0;" :: "n"(N) : "memory");
}
__device__ __forceinline__ void ldm_x4(uint32_t* r, uint32_t addr) {
    asm volatile("ldmatrix.sync.aligned.m8n8.x4.shared.b16 {%0,%1,%2,%3}, [%4];"
                 : "=r"(r[0]), "=r"(r[1]), "=r"(r[2]), "=r"(r[3]) : "r"(addr));
}
__device__ __forceinline__ void mma16816(float* d, const uint32_t* a,
                                         const uint32_t* b) {
    asm volatile(
        "mma.sync.aligned.m16n8k16.row.col.f32.bf16.bf16.f32 "
        "{%0,%1,%2,%3}, {%4,%5,%6,%7}, {%8,%9}, {%0,%1,%2,%3};"
        : "+f"(d[0]), "+f"(d[1]), "+f"(d[2]), "+f"(d[3])
        : "r"(a[0]), "r"(a[1]), "r"(a[2]), "r"(a[3]), "r"(b[0]), "r"(b[1]));
}
// Swizzled smem tile offset: rows of 512B (256 bf16), XOR-swizzle inside 128B.
__device__ __forceinline__ uint32_t tile_off(int r, int kbyte) {
    return (uint32_t)(r * 512 + (kbyte & ~127) + ((kbyte & 127) ^ ((r & 7) << 4)));
}

#define SM_A      0
#define SM_B(p)   (131072 + (p) * 32768)
#define SMEM_TOTAL (131072 + 2 * 32768)   // 192 KB

// ---------------------------------------------------------------------------
// Kernel 1: codebook norms + bf16 conversion. One warp per codebook row.
// ---------------------------------------------------------------------------
__global__ void prep_kernel(const float* __restrict__ E, int K)
{
    int row = (int)((blockIdx.x * blockDim.x + threadIdx.x) >> 5);
    int lane = threadIdx.x & 31;
    if (row >= K) return;
    const float4* p = (const float4*)(E + (size_t)row * DD);
    float4 a = p[lane], b = p[lane + 32];
    float s = a.x*a.x + a.y*a.y + a.z*a.z + a.w*a.w
            + b.x*b.x + b.y*b.y + b.z*b.z + b.w*b.w;
    #pragma unroll
    for (int o = 16; o > 0; o >>= 1) s += __shfl_xor_sync(0xffffffffu, s, o);

    __nv_bfloat162* dst = (__nv_bfloat162*)(g_Ebf + (size_t)row * DD);
    dst[2*lane + 0]      = __float22bfloat162_rn(make_float2(a.x, a.y));
    dst[2*lane + 1]      = __float22bfloat162_rn(make_float2(a.z, a.w));
    dst[2*(lane+32) + 0] = __float22bfloat162_rn(make_float2(b.x, b.y));
    dst[2*(lane+32) + 1] = __float22bfloat162_rn(make_float2(b.z, b.w));

    if (lane == 0) g_C[row] = s;
}

// ---------------------------------------------------------------------------
// Kernel 2: bf16 HMMA GEMM (z @ E^T) + per-token top-2-per-stripe.
// CTA: 256 tokens x 64 codes per iter, 64 iters. 8 warps, 64x32 warp tiles.
// A staged from fp32 z with inline bf16 convert (resident); B double-buffered.
// ---------------------------------------------------------------------------
#define TOP2(q, s, c) do {                                                    \
    if ((s) < tv[q][1]) {                                                     \
        if ((s) < tv[q][0]) { tv[q][1]=tv[q][0]; ti[q][1]=ti[q][0];           \
                              tv[q][0]=(s); ti[q][0]=(c); }                   \
        else { tv[q][1]=(s); ti[q][1]=(c); }                                  \
    } } while (0)

__global__ __launch_bounds__(256, 1) void vq_mma_kernel(const float* __restrict__ z)
{
    extern __shared__ char smem[];
    const uint32_t sa = smem_u32(smem);
    const int tid = threadIdx.x;
    const int row0 = blockIdx.x * TM;

    // ---- B tile 0 via cp.async (overlaps with A conversion below) ----
    {
        const char* srcB = (const char*)g_Ebf;
        #pragma unroll
        for (int i = 0; i < 8; i++) {          // 64 rows x 32 chunks / 256 thr
            int idx = i * 256 + tid;
            int r = idx >> 5, c = idx & 31;
            cp16(sa + SM_B(0) + tile_off(r, c * 16), srcB + (size_t)r * 512 + c * 16);
        }
        cp_commit();
    }

    // ---- stage A: read fp32 z, convert to bf16 into swizzled smem ----
    {
        const float4* srcZ = (const float4*)(z + (size_t)row0 * DD);
        #pragma unroll
        for (int i = 0; i < 64; i++) {         // 256 rows x 64 float4 / 256 thr
            int idx = i * 256 + tid;
            int r = idx >> 6, c = idx & 63;    // c: float4 index within row
            float4 f = srcZ[(size_t)r * 64 + c];
            __nv_bfloat162 h0 = __float22bfloat162_rn(make_float2(f.x, f.y));
            __nv_bfloat162 h1 = __float22bfloat162_rn(make_float2(f.z, f.w));
            uint2 v = make_uint2(*reinterpret_cast<uint32_t*>(&h0),
                                 *reinterpret_cast<uint32_t*>(&h1));
            *(uint2*)(smem + SM_A + tile_off(r, c * 8)) = v;
        }
    }

    const int l = tid & 31, w = tid >> 5;
    const int wm = w >> 1, wn = w & 1;        // 4 m-stripes x 2 n-stripes

    float tv[8][2]; int ti[8][2];
    #pragma unroll
    for (int q = 0; q < 8; q++) {
        tv[q][0] = tv[q][1] = CUDART_INF_F;
        ti[q][0] = ti[q][1] = 0x7fffffff;
    }

    const int a_r  = l & 15;
    const int a_kb = (l >> 4) * 16;
    const int b_r  = ((l >> 4) << 3) + (l & 7);
    const int b_kb = ((l >> 3) & 1) * 16;

    float acc[4][4][4];

    for (int kb = 0; kb < NKB; kb++) {
        if (kb < NKB - 1) {   // prefetch next B tile
            const char* srcB = (const char*)g_Ebf + (size_t)(kb + 1) * TNB * 512;
            uint32_t db = sa + SM_B((kb + 1) & 1);
            #pragma unroll
            for (int i = 0; i < 8; i++) {
                int idx = i * 256 + tid;
                int r = idx >> 5, c = idx & 31;
                cp16(db + tile_off(r, c * 16), srcB + (size_t)r * 512 + c * 16);
            }
            cp_commit();
            cp_wait<1>();
        } else {
            cp_wait<0>();
        }
        __syncthreads();

        const uint32_t sB = sa + SM_B(kb & 1);

        #pragma unroll
        for (int mi = 0; mi < 4; mi++)
            #pragma unroll
            for (int ni = 0; ni < 4; ni++)
                #pragma unroll
                for (int j = 0; j < 4; j++) acc[mi][ni][j] = 0.f;

        #pragma unroll
        for (int ks = 0; ks < 16; ks++) {
            const int k0b = ks * 32;
            uint32_t afrag[4][4];
            #pragma unroll
            for (int mi = 0; mi < 4; mi++)
                ldm_x4(afrag[mi],
                       sa + SM_A + tile_off(wm * 64 + mi * 16 + a_r, k0b + a_kb));
            uint32_t bfrag[4][2];
            #pragma unroll
            for (int nj = 0; nj < 2; nj++) {
                uint32_t t4[4];
                ldm_x4(t4, sB + tile_off(wn * 32 + nj * 16 + b_r, k0b + b_kb));
                bfrag[2*nj][0]   = t4[0]; bfrag[2*nj][1]   = t4[1];
                bfrag[2*nj+1][0] = t4[2]; bfrag[2*nj+1][1] = t4[3];
            }
            #pragma unroll
            for (int mi = 0; mi < 4; mi++)
                #pragma unroll
                for (int ni = 0; ni < 4; ni++)
                    mma16816(acc[mi][ni], afrag[mi], bfrag[ni]);
        }

        // epilogue: s = -2*m + ||e||^2 ; per-row top2
        #pragma unroll
        for (int ni = 0; ni < 4; ni++) {
            const int c0 = kb * TNB + wn * 32 + ni * 8 + (l & 3) * 2;
            const float2 C2 = __ldg((const float2*)(g_C + c0));
            #pragma unroll
            for (int mi = 0; mi < 4; mi++) {
                #pragma unroll
                for (int half = 0; half < 2; half++) {
                    const int q = mi * 2 + half;
                    float s0 = fmaf(-2.f, acc[mi][ni][half * 2 + 0], C2.x);
                    float s1 = fmaf(-2.f, acc[mi][ni][half * 2 + 1], C2.y);
                    TOP2(q, s0, c0);
                    TOP2(q, s1, c0 + 1);
                }
            }
        }
        __syncthreads();   // protect B buffer before next prefetch overwrites
    }

    // write 16 candidates per token (2 n-warps x 4 lane-cols x 2 entries)
    #pragma unroll
    for (int q = 0; q < 8; q++) {
        const int mi = q >> 1, half = q & 1;
        const int r = row0 + wm * 64 + mi * 16 + (l >> 2) + half * 8;
        const int base = r * 16 + wn * 8 + (l & 3) * 2;
        g_cv[base]     = tv[q][0];  g_cv[base + 1] = tv[q][1];
        g_ci[base]     = ti[q][0];  g_ci[base + 1] = ti[q][1];
    }
}

// ---------------------------------------------------------------------------
// Kernel 3: exact rescore of near-tie candidates (reference rounding
// fl(fl(A - 2m) + C), lowest-index tie-break). One warp per token.
// ||z||^2 computed inline (same shuffle-tree order as before).
// ---------------------------------------------------------------------------
__global__ void rescore_kernel(const float* __restrict__ z,
                               const float* __restrict__ E, int T)
{
    int warp = (int)((blockIdx.x * blockDim.x + threadIdx.x) >> 5);
    int lane = threadIdx.x & 31;
    if (warp >= T) return;
    const size_t t = (size_t)warp;

    float vL = CUDART_INF_F; int iL = 0x7fffffff;
    if (lane < 16) { vL = g_cv[t * 16 + lane]; iL = g_ci[t * 16 + lane]; }
    float v0 = vL;
    #pragma unroll
    for (int o = 16; o > 0; o >>= 1)
        v0 = fminf(v0, __shfl_xor_sync(0xffffffffu, v0, o));
    const float thr = v0 + 1.5e-4f;
    unsigned mask = __ballot_sync(0xffffffffu, vL <= thr);

    int besti;
    if (__popc(mask) == 1) {
        besti = __shfl_sync(0xffffffffu, iL, __ffs(mask) - 1);
    } else {
        const float4* zp = (const float4*)(z + t * DD);
        float4 z0 = zp[lane], z1 = zp[lane + 32];
        // ||z||^2, identical op order to the previously-passing prep kernel
        float A = z0.x*z0.x + z0.y*z0.y + z0.z*z0.z + z0.w*z0.w
                + z1.x*z1.x + z1.y*z1.y + z1.z*z1.z + z1.w*z1.w;
        #pragma unroll
        for (int o = 16; o > 0; o >>= 1)
            A += __shfl_xor_sync(0xffffffffu, A, o);

        float bd = CUDART_INF_F; besti = 0x7fffffff;
        #pragma unroll 1
        for (int c = 0; c < 16; c++) {
            if (!((mask >> c) & 1u)) continue;
            int ic = __shfl_sync(0xffffffffu, iL, c);
            const float4* ep = (const float4*)(E + (size_t)ic * DD);
            float4 e0 = ep[lane], e1 = ep[lane + 32];
            float pm = z0.x*e0.x + z0.y*e0.y + z0.z*e0.z + z0.w*e0.w
                     + z1.x*e1.x + z1.y*e1.y + z1.z*e1.z + z1.w*e1.w;
            #pragma unroll
            for (int o = 16; o > 0; o >>= 1)
                pm += __shfl_xor_sync(0xffffffffu, pm, o);
            float d = fmaf(-2.0f, pm, A) + g_C[ic];
            if (d < bd || (d == bd && ic < besti)) { bd = d; besti = ic; }
        }
    }
    if (lane == 0) g_idx[t] = besti;
}

// ---------------------------------------------------------------------------
// Kernel 4: gather quantized rows, write indices, loss partials.
// Per-thread fp32 accumulation; block reduction in double.
// ---------------------------------------------------------------------------
__global__ void vq_gather_kernel(const float* __restrict__ z,
                                 const float* __restrict__ E,
                                 float* __restrict__ out,
                                 int T, int with_idx)
{
    __shared__ double sred[256];
    int tid = threadIdx.x;
    int rbase = blockIdx.x * 32;
    float acc = 0.0f;
    #pragma unroll 4
    for (int rr = 0; rr < 32; rr++) {
        int row = rbase + rr;
        int k = g_idx[row];
        float e  = __ldg(E + (size_t)k * DD + tid);
        float zv = __ldg(z + (size_t)row * DD + tid);
        out[(size_t)row * DD + tid] = e;
        float dlt = e - zv;
        acc = fmaf(dlt, dlt, acc);
        if (with_idx && tid == 0) out[(size_t)T * DD + row] = (float)k;
    }
    sred[tid] = (double)acc;
    __syncthreads();
    #pragma unroll
    for (int o = 128; o > 0; o >>= 1) {
        if (tid < o) sred[tid] += sred[tid + o];
        __syncthreads();
    }
    if (tid == 0) g_part[blockIdx.x] = sred[0];
}

__global__ void vq_loss_kernel(float* __restrict__ out, int T, int npart)
{
    __shared__ double sred[256];
    int tid = threadIdx.x;
    double acc = 0.0;
    for (int i = tid; i < npart; i += 256) acc += g_part[i];
    sred[tid] = acc;
    __syncthreads();
    #pragma unroll
    for (int o = 128; o > 0; o >>= 1) {
        if (tid < o) sred[tid] += sred[tid + o];
        __syncthreads();
    }
    if (tid == 0) {
        float m = (float)(sred[0] / ((double)T * (double)DD));
        out[(size_t)T * DD + T] = m + 0.25f * m;
    }
}

// ---------------------------------------------------------------------------
extern "C" void kernel_launch(void* const* d_in, const int* in_sizes, int n_in,
                              void* d_out, int out_size)
{
    const float* z = (const float*)d_in[0];
    const float* E = (const float*)d_in[1];
    float* out = (float*)d_out;

    int T = in_sizes[0] / DD;   // 65536
    int K = in_sizes[1] / DD;   // 4096

    prep_kernel<<<(K * 32 + 255) / 256, 256>>>(E, K);

    cudaFuncSetAttribute(vq_mma_kernel,
                         cudaFuncAttributeMaxDynamicSharedMemorySize, SMEM_TOTAL);
    vq_mma_kernel<<<T / TM, 256, SMEM_TOTAL>>>(z);

    rescore_kernel<<<T / 8, 256>>>(z, E, T);

    long long need_idx = (long long)T * DD + T;
    int with_idx = (out_size >= need_idx) ? 1 : 0;
    vq_gather_kernel<<<T / 32, 256>>>(z, E, out, T, with_idx);

    if (out_size >= need_idx + 1)
        vq_loss_kernel<<<1, 256>>>(out, T, T / 32);
}